// round 12
// baseline (speedup 1.0000x reference)
#include <cuda_runtime.h>
#include <cuda_bf16.h>
#include <cstdint>

// Problem constants (from reference_code)
constexpr int NNB     = 16;        // N_NEIGH
constexpr int NFEAT   = 32;        // N_FEAT
constexpr int ROW     = 3 + 3 * NFEAT;   // 99 features per pair
constexpr int PAIRS   = NNB * NNB - NNB; // 240 off-diagonal pairs
constexpr int PER_C   = PAIRS * ROW;     // 23760 floats per center

// CTA-wide slab staging: 80 pairs per slab (8 warps x 10 pairs), 3 slabs/center
constexpr int SLAB_PAIRS  = 80;
constexpr int NSLABS      = PAIRS / SLAB_PAIRS;     // 3
constexpr int SLAB_FLOATS = SLAB_PAIRS * ROW;       // 7920
constexpr int SLAB_BYTES  = SLAB_FLOATS * 4;        // 31680 (16B multiple)
constexpr int PPW         = SLAB_PAIRS / 8;         // 10 pairs per warp per slab

constexpr int CPC = 4;   // adjacent centers per CTA (contiguous 380KB output)

__global__ void __launch_bounds__(256)
ang_desc_kernel(const float* __restrict__ atoms_xyz,   // [N_ATOMS,3]
                const float* __restrict__ embed,       // [N_TYPES,32]
                const float* __restrict__ dist,        // [C,16]
                const int*   __restrict__ types,       // [N_ATOMS]
                const int*   __restrict__ i_idx,       // [C]
                const int*   __restrict__ j_idx,       // [C,16]
                float*       __restrict__ out,         // [C,240,99]
                float*       __restrict__ centers_out, // [C]
                int C)
{
    const int t = threadIdx.x;

    __shared__ float s_d[NNB];
    __shared__ float s_inv[NNB];
    __shared__ float s_embi[NFEAT];
    __shared__ float s_embj[NNB * NFEAT]; // neighbor embeddings pre-scaled by 1/d
    __shared__ float s_norm[NNB * NNB];   // d_jk_norm, indexed q = j*16+k
    __shared__ float s_x[NNB], s_y[NNB], s_z[NNB];
    __shared__ int   s_tj[NNB];
    // double-buffered CTA-wide slab: 2 x 31680 B (parity carries across centers)
    __shared__ __align__(16) float s_stage[2][SLAB_FLOATS];

    const int warp = t >> 5;
    const int lane = t & 31;
    const int rot  = (lane - 3) & 31;
    const bool l0 = (lane == 0), l1 = (lane == 1), l2 = (lane == 2);
    const bool llt3 = (lane < 3);

    uint64_t policy;
    asm volatile("createpolicy.fractional.L2::evict_first.b64 %0, 1.0;"
                 : "=l"(policy));

    int it = 0;  // slab counter: s_stage parity carries across all centers

    #pragma unroll 1
    for (int cc = 0; cc < CPC; ++cc) {
        const int c = blockIdx.x * CPC + cc;   // ADJACENT centers per CTA
        if (c >= C) break;

        // ---- prologue: register-chained gathers, one sync ----
        // (overlaps previous center's in-flight bulk stores: its last commit
        // was issued without a trailing wait)
        if (t < NNB) {
            float d = dist[c * NNB + t];
            int   a = j_idx[c * NNB + t];
            s_d[t]   = d;
            s_inv[t] = 1.0f / d;
            s_x[t]  = atoms_xyz[a * 3 + 0];
            s_y[t]  = atoms_xyz[a * 3 + 1];
            s_z[t]  = atoms_xyz[a * 3 + 2];
            s_tj[t] = types[a];
        } else if (t >= 32 && t < 64) {
            int ln = t - 32;
            int ai = i_idx[c];            // broadcast
            int ti = types[ai];           // broadcast
            s_embi[ln] = embed[ti * NFEAT + ln];
            if (ln == 0) centers_out[c] = (float)ai;
        }
        __syncthreads();

        // ---- tables: scaled neighbor embeddings + d_jk_norm ----
        for (int idx = t; idx < NNB * NFEAT; idx += 256) {
            int nb = idx >> 5;
            int f  = idx & 31;
            s_embj[idx] = embed[s_tj[nb] * NFEAT + f] * s_inv[nb];
        }
        {
            int j = t >> 4, k = t & 15;
            float dx = s_x[j] - s_x[k];
            float dy = s_y[j] - s_y[k];
            float dz = s_z[j] - s_z[k];
            float djk = sqrtf(dx * dx + dy * dy + dz * dz);
            float dj = s_d[j], dk = s_d[k];
            float mx = fmaxf(dj, dk), mn = fminf(dj, dk);
            s_norm[t] = (djk - mx + mn) / (2.0f * mn);
        }
        __syncthreads();

        const float embi_a = s_embi[rot];
        const float embi_b = s_embi[(29 + lane) < NFEAT ? (29 + lane) : 0];
        char* gbase = (char*)(out + (size_t)c * PER_C);

        // ---- build 80-pair slabs, drain each via ONE 31.7KB cp.async.bulk ----
        for (int s = 0; s < NSLABS; ++s, ++it) {
            float* buf = s_stage[it & 1];

            // Guard buffer reuse HERE (pre-build): the bulk read of this buffer
            // was committed 2 slabs ago and has had maximal time to drain.
            if (it >= 2) {
                if (t == 0)
                    asm volatile("cp.async.bulk.wait_group 1;" ::: "memory");
                __syncthreads();
            }

            #pragma unroll
            for (int r = 0; r < PPW; ++r) {
                const int rp = warp * PPW + r;       // row within slab
                const int p  = s * SLAB_PAIRS + rp;  // global pair index
                const int q  = p + (p >> 4) + 1;     // skip-diagonal flat index
                const int j  = q >> 4;
                const int k  = q & 15;

                const float dj  = s_d[j];
                const float dk  = s_d[k];
                const float njk = s_norm[q];
                const float ejv = s_embj[j * NFEAT + rot];
                const float ekv = s_embj[k * NFEAT + rot];

                float v0 = embi_a;               // [dj, dk, njk, emb_i[0..28]]
                if (l2) v0 = njk;
                if (l1) v0 = dk;
                if (l0) v0 = dj;
                float v1 = llt3 ? embi_b : ejv;  // [emb_i[29..31], e_j[0..28]]
                float v2 = llt3 ? ejv    : ekv;  // [e_j[29..31],  e_k[0..28]]

                float* rb = buf + rp * ROW;
                rb[lane]      = v0;
                rb[32 + lane] = v1;
                rb[64 + lane] = v2;
                if (llt3) rb[96 + lane] = ekv;   // e_k[29..31]
            }

            __syncthreads();   // slab fully built
            if (t == 0) {
                asm volatile("fence.proxy.async.shared::cta;" ::: "memory");
                uint32_t saddr = (uint32_t)__cvta_generic_to_shared(buf);
                asm volatile(
                    "cp.async.bulk.global.shared::cta.bulk_group.L2::cache_hint"
                    " [%0], [%1], %2, %3;"
                    :: "l"(gbase + (size_t)s * SLAB_BYTES), "r"(saddr),
                       "n"(SLAB_BYTES), "l"(policy)
                    : "memory");
                asm volatile("cp.async.bulk.commit_group;" ::: "memory");
            }
            // no wait after commit — next pre-build guard / exit drain orders it
        }
        // no full drain between centers — pipeline carries over
    }

    // SMEM handed to next CTA on this SM: drain fully before exit
    __syncthreads();
    if (t == 0)
        asm volatile("cp.async.bulk.wait_group 0;" ::: "memory");
}

extern "C" void kernel_launch(void* const* d_in, const int* in_sizes, int n_in,
                              void* d_out, int out_size)
{
    const float* atoms_xyz = (const float*)d_in[0];
    const float* embed     = (const float*)d_in[1];
    const float* dist      = (const float*)d_in[2];
    const int*   types     = (const int*)  d_in[3];
    const int*   i_idx     = (const int*)  d_in[4];
    const int*   j_idx     = (const int*)  d_in[5];

    const int C = in_sizes[4];                 // number of centers
    float* out = (float*)d_out;
    float* centers_out = out + (size_t)C * PER_C;

    int grid = (C + CPC - 1) / CPC;            // 4 adjacent centers per CTA

    ang_desc_kernel<<<grid, 256>>>(atoms_xyz, embed, dist, types,
                                   i_idx, j_idx, out, centers_out, C);
}

// round 13
// speedup vs baseline: 1.0325x; 1.0325x over previous
#include <cuda_runtime.h>
#include <cuda_bf16.h>
#include <cstdint>

// Problem constants (from reference_code)
constexpr int NNB     = 16;        // N_NEIGH
constexpr int NFEAT   = 32;        // N_FEAT
constexpr int ROW     = 3 + 3 * NFEAT;   // 99 features per pair
constexpr int PAIRS   = NNB * NNB - NNB; // 240 off-diagonal pairs
constexpr int PER_C   = PAIRS * ROW;     // 23760 floats per center

// CTA-wide slab staging: 80 pairs per slab (8 warps x 10 pairs), 3 slabs/center
constexpr int SLAB_PAIRS  = 80;
constexpr int NSLABS      = PAIRS / SLAB_PAIRS;     // 3
constexpr int SLAB_FLOATS = SLAB_PAIRS * ROW;       // 7920
constexpr int SLAB_BYTES  = SLAB_FLOATS * 4;        // 31680 (16B multiple)
constexpr int PPW         = SLAB_PAIRS / 8;         // 10 pairs per warp per slab

constexpr int CPC = 2;   // adjacent centers per CTA (contiguous 190KB output)

__global__ void __launch_bounds__(256)
ang_desc_kernel(const float* __restrict__ atoms_xyz,   // [N_ATOMS,3]
                const float* __restrict__ embed,       // [N_TYPES,32]
                const float* __restrict__ dist,        // [C,16]
                const int*   __restrict__ types,       // [N_ATOMS]
                const int*   __restrict__ i_idx,       // [C]
                const int*   __restrict__ j_idx,       // [C,16]
                float*       __restrict__ out,         // [C,240,99]
                float*       __restrict__ centers_out, // [C]
                int C)
{
    const int t = threadIdx.x;

    __shared__ float s_d[NNB];
    __shared__ float s_inv[NNB];
    __shared__ float s_embi[NFEAT];
    __shared__ float s_embj[NNB * NFEAT]; // neighbor embeddings pre-scaled by 1/d
    __shared__ float s_norm[NNB * NNB];   // d_jk_norm, indexed q = j*16+k
    __shared__ float s_x[NNB], s_y[NNB], s_z[NNB];
    __shared__ int   s_tj[NNB];
    // double-buffered CTA-wide slab: 2 x 31680 B (parity carries across centers)
    __shared__ __align__(16) float s_stage[2][SLAB_FLOATS];

    const int warp = t >> 5;
    const int lane = t & 31;
    const int rot  = (lane - 3) & 31;
    const bool l0 = (lane == 0), l1 = (lane == 1), l2 = (lane == 2);
    const bool llt3 = (lane < 3);

    uint64_t policy;
    asm volatile("createpolicy.fractional.L2::evict_first.b64 %0, 1.0;"
                 : "=l"(policy));

    int it = 0;  // slab counter: s_stage parity carries across both centers

    #pragma unroll 1
    for (int cc = 0; cc < CPC; ++cc) {
        const int c = blockIdx.x * CPC + cc;   // two ADJACENT centers per CTA
        if (c >= C) break;

        // ---- prologue: register-chained gathers, one sync ----
        // Slab-0's buffer-reuse guard is folded in here: t0's wait_group
        // overlaps the gather latency chain, and the prologue's sync
        // publishes it to all warps (saves a barrier pair per center).
        if (t < NNB) {
            float d = dist[c * NNB + t];
            int   a = j_idx[c * NNB + t];
            s_d[t]   = d;
            s_inv[t] = 1.0f / d;
            s_x[t]  = atoms_xyz[a * 3 + 0];
            s_y[t]  = atoms_xyz[a * 3 + 1];
            s_z[t]  = atoms_xyz[a * 3 + 2];
            s_tj[t] = types[a];
        } else if (t >= 32 && t < 64) {
            int ln = t - 32;
            int ai = i_idx[c];            // broadcast
            int ti = types[ai];           // broadcast
            s_embi[ln] = embed[ti * NFEAT + ln];
            if (ln == 0) centers_out[c] = (float)ai;
        } else if (t == 64 && it >= 2) {
            // guard for slab 0 of this center: commit (it-2) must be drained.
            // NOTE: t==64 never commits; only t==0 does. Bulk-group state is
            // per-thread, so the wait must be on t0 — redirect below.
        }
        if (t == 0 && it >= 2)
            asm volatile("cp.async.bulk.wait_group 1;" ::: "memory");
        __syncthreads();

        // ---- tables: scaled neighbor embeddings + d_jk_norm ----
        for (int idx = t; idx < NNB * NFEAT; idx += 256) {
            int nb = idx >> 5;
            int f  = idx & 31;
            s_embj[idx] = embed[s_tj[nb] * NFEAT + f] * s_inv[nb];
        }
        {
            int j = t >> 4, k = t & 15;
            float dx = s_x[j] - s_x[k];
            float dy = s_y[j] - s_y[k];
            float dz = s_z[j] - s_z[k];
            float djk = sqrtf(dx * dx + dy * dy + dz * dz);
            float dj = s_d[j], dk = s_d[k];
            float mx = fmaxf(dj, dk), mn = fminf(dj, dk);
            s_norm[t] = (djk - mx + mn) / (2.0f * mn);
        }
        __syncthreads();

        const float embi_a = s_embi[rot];
        const float embi_b = s_embi[(29 + lane) < NFEAT ? (29 + lane) : 0];
        char* gbase = (char*)(out + (size_t)c * PER_C);

        // ---- build 80-pair slabs, drain each via ONE 31.7KB cp.async.bulk ----
        for (int s = 0; s < NSLABS; ++s, ++it) {
            float* buf = s_stage[it & 1];

            // Pre-build buffer-reuse guard for slabs 1,2 (slab 0's guard was
            // folded into the prologue above).
            if (s > 0 && it >= 2) {
                if (t == 0)
                    asm volatile("cp.async.bulk.wait_group 1;" ::: "memory");
                __syncthreads();
            }

            #pragma unroll
            for (int r = 0; r < PPW; ++r) {
                const int rp = warp * PPW + r;       // row within slab
                const int p  = s * SLAB_PAIRS + rp;  // global pair index
                const int q  = p + (p >> 4) + 1;     // skip-diagonal flat index
                const int j  = q >> 4;
                const int k  = q & 15;

                const float dj  = s_d[j];
                const float dk  = s_d[k];
                const float njk = s_norm[q];
                const float ejv = s_embj[j * NFEAT + rot];
                const float ekv = s_embj[k * NFEAT + rot];

                float v0 = embi_a;               // [dj, dk, njk, emb_i[0..28]]
                if (l2) v0 = njk;
                if (l1) v0 = dk;
                if (l0) v0 = dj;
                float v1 = llt3 ? embi_b : ejv;  // [emb_i[29..31], e_j[0..28]]
                float v2 = llt3 ? ejv    : ekv;  // [e_j[29..31],  e_k[0..28]]

                float* rb = buf + rp * ROW;
                rb[lane]      = v0;
                rb[32 + lane] = v1;
                rb[64 + lane] = v2;
                if (llt3) rb[96 + lane] = ekv;   // e_k[29..31]
            }

            __syncthreads();   // slab fully built
            if (t == 0) {
                asm volatile("fence.proxy.async.shared::cta;" ::: "memory");
                uint32_t saddr = (uint32_t)__cvta_generic_to_shared(buf);
                asm volatile(
                    "cp.async.bulk.global.shared::cta.bulk_group.L2::cache_hint"
                    " [%0], [%1], %2, %3;"
                    :: "l"(gbase + (size_t)s * SLAB_BYTES), "r"(saddr),
                       "n"(SLAB_BYTES), "l"(policy)
                    : "memory");
                asm volatile("cp.async.bulk.commit_group;" ::: "memory");
            }
            // no wait after commit — next guard / exit drain orders it
        }
        // no full drain between the two centers — pipeline carries over
    }

    // SMEM handed to next CTA on this SM: drain fully before exit
    __syncthreads();
    if (t == 0)
        asm volatile("cp.async.bulk.wait_group 0;" ::: "memory");
}

extern "C" void kernel_launch(void* const* d_in, const int* in_sizes, int n_in,
                              void* d_out, int out_size)
{
    const float* atoms_xyz = (const float*)d_in[0];
    const float* embed     = (const float*)d_in[1];
    const float* dist      = (const float*)d_in[2];
    const int*   types     = (const int*)  d_in[3];
    const int*   i_idx     = (const int*)  d_in[4];
    const int*   j_idx     = (const int*)  d_in[5];

    const int C = in_sizes[4];                 // number of centers
    float* out = (float*)d_out;
    float* centers_out = out + (size_t)C * PER_C;

    int grid = (C + CPC - 1) / CPC;            // 2 adjacent centers per CTA

    ang_desc_kernel<<<grid, 256>>>(atoms_xyz, embed, dist, types,
                                   i_idx, j_idx, out, centers_out, C);
}

// round 14
// speedup vs baseline: 1.0566x; 1.0233x over previous
#include <cuda_runtime.h>
#include <cuda_bf16.h>
#include <cstdint>

// Problem constants (from reference_code)
constexpr int NNB     = 16;        // N_NEIGH
constexpr int NFEAT   = 32;        // N_FEAT
constexpr int ROW     = 3 + 3 * NFEAT;   // 99 features per pair
constexpr int PAIRS   = NNB * NNB - NNB; // 240 off-diagonal pairs
constexpr int PER_C   = PAIRS * ROW;     // 23760 floats per center

// CTA-wide slab staging: 80 pairs per slab (8 warps x 10 pairs), 3 slabs/center
constexpr int SLAB_PAIRS  = 80;
constexpr int NSLABS      = PAIRS / SLAB_PAIRS;     // 3
constexpr int SLAB_FLOATS = SLAB_PAIRS * ROW;       // 7920
constexpr int SLAB_BYTES  = SLAB_FLOATS * 4;        // 31680 (16B multiple)
constexpr int PPW         = SLAB_PAIRS / 8;         // 10 pairs per warp per slab

__global__ void __launch_bounds__(256)
ang_desc_kernel(const float* __restrict__ atoms_xyz,   // [N_ATOMS,3]
                const float* __restrict__ embed,       // [N_TYPES,32]
                const float* __restrict__ dist,        // [C,16]
                const int*   __restrict__ types,       // [N_ATOMS]
                const int*   __restrict__ i_idx,       // [C]
                const int*   __restrict__ j_idx,       // [C,16]
                float*       __restrict__ out,         // [C,240,99]
                float*       __restrict__ centers_out) // [C]
{
    const int c = blockIdx.x;                // one center per CTA (best-benched)
    const int t = threadIdx.x;

    __shared__ float s_d[NNB];
    __shared__ float s_inv[NNB];
    __shared__ float s_embi[NFEAT];
    __shared__ float s_embj[NNB * NFEAT]; // neighbor embeddings pre-scaled by 1/d
    __shared__ float s_norm[NNB * NNB];   // d_jk_norm, indexed q = j*16+k
    __shared__ float s_x[NNB], s_y[NNB], s_z[NNB];
    __shared__ int   s_tj[NNB];
    // double-buffered CTA-wide slab: 2 x 31680 B
    __shared__ __align__(16) float s_stage[2][SLAB_FLOATS];

    // ---- prologue: register-chained gathers, one sync ----
    if (t < NNB) {
        float d = dist[c * NNB + t];
        int   a = j_idx[c * NNB + t];
        s_d[t]   = d;
        s_inv[t] = 1.0f / d;
        s_x[t]  = atoms_xyz[a * 3 + 0];
        s_y[t]  = atoms_xyz[a * 3 + 1];
        s_z[t]  = atoms_xyz[a * 3 + 2];
        s_tj[t] = types[a];
    } else if (t >= 32 && t < 64) {
        int ln = t - 32;
        int ai = i_idx[c];            // broadcast
        int ti = types[ai];           // broadcast
        s_embi[ln] = embed[ti * NFEAT + ln];
        if (ln == 0) centers_out[c] = (float)ai;
    }
    __syncthreads();

    // ---- tables: scaled neighbor embeddings + d_jk_norm ----
    for (int idx = t; idx < NNB * NFEAT; idx += 256) {
        int nb = idx >> 5;
        int f  = idx & 31;
        s_embj[idx] = embed[s_tj[nb] * NFEAT + f] * s_inv[nb];
    }
    {
        int j = t >> 4, k = t & 15;
        float dx = s_x[j] - s_x[k];
        float dy = s_y[j] - s_y[k];
        float dz = s_z[j] - s_z[k];
        float djk = sqrtf(dx * dx + dy * dy + dz * dz);
        float dj = s_d[j], dk = s_d[k];
        float mx = fmaxf(dj, dk), mn = fminf(dj, dk);
        s_norm[t] = (djk - mx + mn) / (2.0f * mn);
    }
    __syncthreads();

    // ---- build 80-pair slabs, drain each via ONE 31.7KB cp.async.bulk with
    // L2 evict_first. Buffer-reuse wait hoisted to PRE-BUILD (R11 win): with
    // 3 slabs only slab 2 needs a guard (buffer 0 reuse); the final commits
    // drain under CTA exit / next-CTA launch overlap. ----
    const int warp = t >> 5;
    const int lane = t & 31;
    const int rot  = (lane - 3) & 31;

    const float embi_a = s_embi[rot];
    const float embi_b = s_embi[(29 + lane) < NFEAT ? (29 + lane) : 0];
    const bool  l0 = (lane == 0), l1 = (lane == 1), l2 = (lane == 2);
    const bool  llt3 = (lane < 3);

    char* gbase = (char*)(out + (size_t)c * PER_C);

    uint64_t policy;
    asm volatile("createpolicy.fractional.L2::evict_first.b64 %0, 1.0;"
                 : "=l"(policy));

    for (int s = 0; s < NSLABS; ++s) {
        float* buf = s_stage[s & 1];

        // Pre-build guard: only slab 2 reuses a buffer (slab 0's). Its commit
        // has had slab 1's entire build+commit to drain already.
        if (s == 2) {
            if (t == 0)
                asm volatile("cp.async.bulk.wait_group 1;" ::: "memory");
            __syncthreads();
        }

        #pragma unroll
        for (int r = 0; r < PPW; ++r) {
            const int rp = warp * PPW + r;       // row within slab
            const int p  = s * SLAB_PAIRS + rp;  // global pair index
            const int q  = p + (p >> 4) + 1;     // skip-diagonal flat index
            const int j  = q >> 4;
            const int k  = q & 15;

            const float dj  = s_d[j];
            const float dk  = s_d[k];
            const float njk = s_norm[q];
            const float ejv = s_embj[j * NFEAT + rot];
            const float ekv = s_embj[k * NFEAT + rot];

            float v0 = embi_a;               // [dj, dk, njk, emb_i[0..28]]
            if (l2) v0 = njk;
            if (l1) v0 = dk;
            if (l0) v0 = dj;
            float v1 = llt3 ? embi_b : ejv;  // [emb_i[29..31], e_j[0..28]]
            float v2 = llt3 ? ejv    : ekv;  // [e_j[29..31],  e_k[0..28]]

            float* rb = buf + rp * ROW;
            rb[lane]      = v0;
            rb[32 + lane] = v1;
            rb[64 + lane] = v2;
            if (llt3) rb[96 + lane] = ekv;   // e_k[29..31]
        }

        __syncthreads();   // slab fully built
        if (t == 0) {
            asm volatile("fence.proxy.async.shared::cta;" ::: "memory");
            uint32_t saddr = (uint32_t)__cvta_generic_to_shared(buf);
            asm volatile(
                "cp.async.bulk.global.shared::cta.bulk_group.L2::cache_hint"
                " [%0], [%1], %2, %3;"
                :: "l"(gbase + (size_t)s * SLAB_BYTES), "r"(saddr),
                   "n"(SLAB_BYTES), "l"(policy)
                : "memory");
            asm volatile("cp.async.bulk.commit_group;" ::: "memory");
        }
        // no wait after commit — pre-build guard / exit drain orders it
        if (s + 1 < NSLABS) __syncthreads();
    }

    // SMEM handed to next CTA on this SM: drain fully before exit
    __syncthreads();
    if (t == 0)
        asm volatile("cp.async.bulk.wait_group 0;" ::: "memory");
}

extern "C" void kernel_launch(void* const* d_in, const int* in_sizes, int n_in,
                              void* d_out, int out_size)
{
    const float* atoms_xyz = (const float*)d_in[0];
    const float* embed     = (const float*)d_in[1];
    const float* dist      = (const float*)d_in[2];
    const int*   types     = (const int*)  d_in[3];
    const int*   i_idx     = (const int*)  d_in[4];
    const int*   j_idx     = (const int*)  d_in[5];

    const int C = in_sizes[4];                 // number of centers
    float* out = (float*)d_out;
    float* centers_out = out + (size_t)C * PER_C;

    ang_desc_kernel<<<C, 256>>>(atoms_xyz, embed, dist, types,
                                i_idx, j_idx, out, centers_out);
}

// round 15
// speedup vs baseline: 1.0584x; 1.0017x over previous
#include <cuda_runtime.h>
#include <cuda_bf16.h>
#include <cstdint>

// Problem constants (from reference_code)
constexpr int NNB     = 16;        // N_NEIGH
constexpr int NFEAT   = 32;        // N_FEAT
constexpr int ROW     = 3 + 3 * NFEAT;   // 99 features per pair
constexpr int PAIRS   = NNB * NNB - NNB; // 240 off-diagonal pairs
constexpr int PER_C   = PAIRS * ROW;     // 23760 floats per center

// CTA-wide slab staging: 80 pairs per slab (8 warps x 10 pairs), 3 slabs/center
constexpr int SLAB_PAIRS  = 80;
constexpr int NSLABS      = PAIRS / SLAB_PAIRS;     // 3
constexpr int SLAB_FLOATS = SLAB_PAIRS * ROW;       // 7920
constexpr int SLAB_BYTES  = SLAB_FLOATS * 4;        // 31680 (16B multiple)
constexpr int PPW         = SLAB_PAIRS / 8;         // 10 pairs per warp per slab

__global__ void __launch_bounds__(256)
ang_desc_kernel(const float* __restrict__ atoms_xyz,   // [N_ATOMS,3]
                const float* __restrict__ embed,       // [N_TYPES,32]
                const float* __restrict__ dist,        // [C,16]
                const int*   __restrict__ types,       // [N_ATOMS]
                const int*   __restrict__ i_idx,       // [C]
                const int*   __restrict__ j_idx,       // [C,16]
                float*       __restrict__ out,         // [C,240,99]
                float*       __restrict__ centers_out) // [C]
{
    const int c = blockIdx.x;                // one center per CTA
    const int t = threadIdx.x;

    __shared__ float s_d[NNB];
    __shared__ float s_inv[NNB];
    __shared__ float s_embi[NFEAT];
    __shared__ float s_embj[NNB * NFEAT]; // neighbor embeddings pre-scaled by 1/d
    __shared__ float s_norm[NNB * NNB];   // d_jk_norm, indexed q = j*16+k
    __shared__ float s_x[NNB], s_y[NNB], s_z[NNB];
    __shared__ int   s_tj[NNB];
    // double-buffered CTA-wide slab: 2 x 31680 B
    __shared__ __align__(16) float s_stage[2][SLAB_FLOATS];

    // ---- prologue: register-chained gathers, one sync ----
    if (t < NNB) {
        float d = dist[c * NNB + t];
        int   a = j_idx[c * NNB + t];
        s_d[t]   = d;
        s_inv[t] = 1.0f / d;
        s_x[t]  = atoms_xyz[a * 3 + 0];
        s_y[t]  = atoms_xyz[a * 3 + 1];
        s_z[t]  = atoms_xyz[a * 3 + 2];
        s_tj[t] = types[a];
    } else if (t >= 32 && t < 64) {
        int ln = t - 32;
        int ai = i_idx[c];            // broadcast
        int ti = types[ai];           // broadcast
        s_embi[ln] = embed[ti * NFEAT + ln];
        if (ln == 0) centers_out[c] = (float)ai;
    }
    __syncthreads();

    // ---- tables: scaled neighbor embeddings + d_jk_norm ----
    for (int idx = t; idx < NNB * NFEAT; idx += 256) {
        int nb = idx >> 5;
        int f  = idx & 31;
        s_embj[idx] = embed[s_tj[nb] * NFEAT + f] * s_inv[nb];
    }
    {
        int j = t >> 4, k = t & 15;
        float dx = s_x[j] - s_x[k];
        float dy = s_y[j] - s_y[k];
        float dz = s_z[j] - s_z[k];
        float djk = sqrtf(dx * dx + dy * dy + dz * dz);
        float dj = s_d[j], dk = s_d[k];
        float mx = fmaxf(dj, dk), mn = fminf(dj, dk);
        s_norm[t] = (djk - mx + mn) / (2.0f * mn);
    }
    __syncthreads();

    // ---- build 80-pair slabs, drain each via ONE 31.7KB cp.async.bulk with
    // L2 evict_first. Minimal barrier set: one build-completion sync per slab,
    // one guard before slab 2's buffer reuse. Post-commit syncs removed: the
    // 7 builder warps start the NEXT buffer while t0 fences/commits this one
    // (different buffer, no hazard; same-buffer reuse guarded by wait_group).
    const int warp = t >> 5;
    const int lane = t & 31;
    const int rot  = (lane - 3) & 31;

    const float embi_a = s_embi[rot];
    const float embi_b = s_embi[(29 + lane) < NFEAT ? (29 + lane) : 0];
    const bool  l0 = (lane == 0), l1 = (lane == 1), l2 = (lane == 2);
    const bool  llt3 = (lane < 3);

    char* gbase = (char*)(out + (size_t)c * PER_C);

    uint64_t policy;
    asm volatile("createpolicy.fractional.L2::evict_first.b64 %0, 1.0;"
                 : "=l"(policy));

    #pragma unroll 1
    for (int s = 0; s < NSLABS; ++s) {
        float* buf = s_stage[s & 1];

        // Pre-build guard: only slab 2 reuses a buffer (slab 0's). t0 reaches
        // here after committing slab 1 (program order), so wait_group 1 leaves
        // exactly slab 1 in flight and proves slab 0 drained.
        if (s == 2) {
            if (t == 0)
                asm volatile("cp.async.bulk.wait_group 1;" ::: "memory");
            __syncthreads();
        }

        #pragma unroll
        for (int r = 0; r < PPW; ++r) {
            const int rp = warp * PPW + r;       // row within slab
            const int p  = s * SLAB_PAIRS + rp;  // global pair index
            const int q  = p + (p >> 4) + 1;     // skip-diagonal flat index
            const int j  = q >> 4;
            const int k  = q & 15;

            const float dj  = s_d[j];
            const float dk  = s_d[k];
            const float njk = s_norm[q];
            const float ejv = s_embj[j * NFEAT + rot];
            const float ekv = s_embj[k * NFEAT + rot];

            float v0 = embi_a;               // [dj, dk, njk, emb_i[0..28]]
            if (l2) v0 = njk;
            if (l1) v0 = dk;
            if (l0) v0 = dj;
            float v1 = llt3 ? embi_b : ejv;  // [emb_i[29..31], e_j[0..28]]
            float v2 = llt3 ? ejv    : ekv;  // [e_j[29..31],  e_k[0..28]]

            float* rb = buf + rp * ROW;
            rb[lane]      = v0;
            rb[32 + lane] = v1;
            rb[64 + lane] = v2;
            if (llt3) rb[96 + lane] = ekv;   // e_k[29..31]
        }

        __syncthreads();   // slab fully built (publishes STS to t0)
        if (t == 0) {
            asm volatile("fence.proxy.async.shared::cta;" ::: "memory");
            uint32_t saddr = (uint32_t)__cvta_generic_to_shared(buf);
            asm volatile(
                "cp.async.bulk.global.shared::cta.bulk_group.L2::cache_hint"
                " [%0], [%1], %2, %3;"
                :: "l"(gbase + (size_t)s * SLAB_BYTES), "r"(saddr),
                   "n"(SLAB_BYTES), "l"(policy)
                : "memory");
            asm volatile("cp.async.bulk.commit_group;" ::: "memory");
        }
        // no post-commit sync: builders proceed to the other buffer at once
    }

    // t0's commits precede this in program order; other threads have no
    // outstanding async obligations. Drain before SMEM is handed to next CTA.
    if (t == 0)
        asm volatile("cp.async.bulk.wait_group 0;" ::: "memory");
}

extern "C" void kernel_launch(void* const* d_in, const int* in_sizes, int n_in,
                              void* d_out, int out_size)
{
    const float* atoms_xyz = (const float*)d_in[0];
    const float* embed     = (const float*)d_in[1];
    const float* dist      = (const float*)d_in[2];
    const int*   types     = (const int*)  d_in[3];
    const int*   i_idx     = (const int*)  d_in[4];
    const int*   j_idx     = (const int*)  d_in[5];

    const int C = in_sizes[4];                 // number of centers
    float* out = (float*)d_out;
    float* centers_out = out + (size_t)C * PER_C;

    ang_desc_kernel<<<C, 256>>>(atoms_xyz, embed, dist, types,
                                i_idx, j_idx, out, centers_out);
}